// round 10
// baseline (speedup 1.0000x reference)
#include <cuda_runtime.h>

// Problem-fixed shapes (setup_inputs): R=4000, C=20, K=3, H=W=1024, h=w=128.
#define HH 1024
#define WW 1024
#define CC 20
#define hh 128
#define ww 128
#define C1 21      // refine_result last dim = C+1
#define EPSF 1e-6f
#define NSEG 64
#define SEGH 16                 // rows per segment
#define MAXB 16384              // events per (c,seg) bucket; hard max = 4*R = 16000
#define PROWS 8                 // rows per smem phase in k_AB (2 phases)
#define PINF 0x7F7FFFFF         // bits of +3.4028e38f
#define NINF 0xFF7FFFFF         // bits of -3.4028e38f

// Static scratch (no runtime allocation). Zero/static-initialized; every
// launch restores the invariant state it started from (self-cleaning).
__device__ int2  g_ev [CC][NSEG][MAXB];     // events (order irrelevant)
__device__ int   g_cnt[CC][NSEG];           // bucket sizes (reset by k_loss)
__device__ int   g_flag[CC][NSEG];          // aggregate-ready flags (reset by k_loss)
__device__ float g_seg[CC][NSEG][WW];       // per-segment column-sum PREFIX over x
__device__ float g_Rm[CC][hh][ww];          // sampled integral-image values
__device__ int   g_minb[CC] = {PINF,PINF,PINF,PINF,PINF,PINF,PINF,PINF,PINF,PINF,
                               PINF,PINF,PINF,PINF,PINF,PINF,PINF,PINF,PINF,PINF};
__device__ int   g_maxb[CC] = {NINF,NINF,NINF,NINF,NINF,NINF,NINF,NINF,NINF,NINF,
                               NINF,NINF,NINF,NINF,NINF,NINF,NINF,NINF,NINF,NINF};

__device__ __forceinline__ void atomicMinF(int* addr, float v) {
    int old = *addr;
    while (__int_as_float(old) > v) {
        int assumed = old;
        old = atomicCAS(addr, assumed, __float_as_int(v));
        if (old == assumed) break;
    }
}
__device__ __forceinline__ void atomicMaxF(int* addr, float v) {
    int old = *addr;
    while (__int_as_float(old) < v) {
        int assumed = old;
        old = atomicCAS(addr, assumed, __float_as_int(v));
        if (old == assumed) break;
    }
}

// ---------------------------------------------------------------------------
// 1) Scores + sparse event emission; also zeroes the output scalar.
//    grid (R/256, CC); invalid channels exit.
__device__ __forceinline__ void emit_row(int c, int y, int x1, float s1, int x2, float s2) {
    if (y >= HH) return;                   // reference clips row H away via M[:H]
    int seg = y >> 4, yl = y & (SEGH - 1);
    int2 e1 = make_int2(x1 | (yl << 10), __float_as_int(s1));
    if (x2 < WW) {
        int idx = atomicAdd(&g_cnt[c][seg], 2);
        g_ev[c][seg][idx]     = e1;
        g_ev[c][seg][idx + 1] = make_int2(x2 | (yl << 10), __float_as_int(s2));
    } else {
        int idx = atomicAdd(&g_cnt[c][seg], 1);
        g_ev[c][seg][idx] = e1;
    }
}

__global__ void k_scatter(const float* __restrict__ refine,
                          const float* __restrict__ rois,
                          const int*   __restrict__ labels,
                          int R, float* __restrict__ out) {
    if (blockIdx.x == 0 && blockIdx.y == 0 && threadIdx.x == 0)
        out[0] = 0.f;                      // k_loss accumulates into this later
    int c = blockIdx.y;
    if (labels[c] != 1) return;            // scores *= vmf
    int r = blockIdx.x * blockDim.x + threadIdx.x;
    if (r >= R) return;
    int base = r * C1 + c + 1;             // avg[:,1:]
    float s = (refine[base] + refine[R * C1 + base] + refine[2 * R * C1 + base]) * (1.0f / 3.0f);
    if (s < 0.3f) return;                  // SCORE_THRES
    int x1 = (int)rois[r * 5 + 1];
    int y1 = (int)rois[r * 5 + 2];
    int x2 = (int)rois[r * 5 + 3];
    int y2 = (int)rois[r * 5 + 4];
    // M(y,x) = sum s * [y1<=y<y2] * [x1<=x<x2]
    emit_row(c, y1, x1,  s, x2, -s);
    emit_row(c, y2, x1, -s, x2,  s);
}

// ---------------------------------------------------------------------------
// 2) Merged segment scan with decoupled lookback. Thread = one column.
//    Bucket-local: smem diff-array scatter + 16 per-row parallel prefixes,
//    tracking cumulative run, min/max-over-rows, sampled rows (base-free).
//    Publish segment aggregate T + flag; wait on predecessors (all lower
//    blockIdx -> launch-order forward progress, CUB-style); base = sum of
//    their aggregates; add base everywhere. grid (NSEG, CC), 1024 thr.
__global__ __launch_bounds__(1024, 2) void k_AB(const int* __restrict__ labels) {
    int c = blockIdx.y;
    if (labels[c] != 1) return;
    int seg = blockIdx.x, x = threadIdx.x;
    int lane = x & 31, warp = x >> 5;

    __shared__ float diff[PROWS][WW];    // 32 KB
    __shared__ float wsum[PROWS][32];    // per-row warp partials -> exclusives
    __shared__ float redmn[32], redmx[32];

    int E = g_cnt[c][seg];
    float runl = 0.f;                    // cumulative column prefix (base-free)
    float cmn = 3.4e38f, cmx = -3.4e38f;
    float samp0 = 0.f, samp1 = 0.f;      // runl at local rows 0 and 8

    #pragma unroll
    for (int p = 0; p < SEGH / PROWS; ++p) {
        #pragma unroll
        for (int r = 0; r < PROWS; ++r) diff[r][x] = 0.f;
        __syncthreads();

        for (int i = x; i < E; i += 1024) {
            int2 e = g_ev[c][seg][i];
            int yl = e.x >> 10;
            if ((yl >> 3) == p)
                atomicAdd(&diff[yl & 7][e.x & 0x3FF], __int_as_float(e.y));
        }
        __syncthreads();

        // Per-row warp scans (8 independent -> ILP hides shfl latency).
        float varr[PROWS];
        #pragma unroll
        for (int r = 0; r < PROWS; ++r) {
            float v = diff[r][x];
            #pragma unroll
            for (int o = 1; o < 32; o <<= 1) {
                float n = __shfl_up_sync(0xFFFFFFFF, v, o);
                if (lane >= o) v += n;
            }
            varr[r] = v;
            if (lane == 31) wsum[r][warp] = v;
        }
        __syncthreads();

        // Warps 0..7 convert their row's warp sums to EXCLUSIVE offsets (parallel).
        if (warp < PROWS) {
            float w = wsum[warp][lane];
            #pragma unroll
            for (int o = 1; o < 32; o <<= 1) {
                float n = __shfl_up_sync(0xFFFFFFFF, w, o);
                if (lane >= o) w += n;
            }
            float excl = __shfl_up_sync(0xFFFFFFFF, w, 1);
            wsum[warp][lane] = (lane == 0) ? 0.f : excl;
        }
        __syncthreads();

        // Accumulate rows in order: P_r = varr[r] + exclusive warp offset.
        #pragma unroll
        for (int r = 0; r < PROWS; ++r) {
            runl += varr[r] + wsum[r][warp];
            cmn = fminf(cmn, runl);
            cmx = fmaxf(cmx, runl);
            if (r == 0) { if (p == 0) samp0 = runl; else samp1 = runl; }
        }
        __syncthreads();                 // smem reuse next phase
    }

    // Publish segment aggregate T = runl (release: fence-all then flag).
    g_seg[c][seg][x] = runl;
    __threadfence();
    __syncthreads();
    if (x == 0) atomicExch(&g_flag[c][seg], 1);

    // Lookback: wait for all predecessors (lower blockIdx -> already launched).
    if (x == 0) {
        for (int s = 0; s < seg; ++s)
            while (atomicAdd(&g_flag[c][s], 0) == 0) {}
        __threadfence();
    }
    __syncthreads();

    // Base = sum of predecessor aggregates (L2-resident, coalesced, batched).
    float base = 0.f;
    {
        int s = 0;
        for (; s + 8 <= seg; s += 8) {
            float v0 = g_seg[c][s + 0][x], v1 = g_seg[c][s + 1][x];
            float v2 = g_seg[c][s + 2][x], v3 = g_seg[c][s + 3][x];
            float v4 = g_seg[c][s + 4][x], v5 = g_seg[c][s + 5][x];
            float v6 = g_seg[c][s + 6][x], v7 = g_seg[c][s + 7][x];
            base += ((v0 + v1) + (v2 + v3)) + ((v4 + v5) + (v6 + v7));
        }
        for (; s < seg; ++s) base += g_seg[c][s][x];
    }

    float mn = base + cmn, mx = base + cmx;
    if ((x & 7) == 0) {                  // sampled columns; rows seg*16+{0,8}
        g_Rm[c][seg * 2 + 0][x >> 3] = base + samp0;
        g_Rm[c][seg * 2 + 1][x >> 3] = base + samp1;
    }

    // Block-wide min/max reduce.
    #pragma unroll
    for (int o = 16; o; o >>= 1) {
        mn = fminf(mn, __shfl_xor_sync(0xFFFFFFFF, mn, o));
        mx = fmaxf(mx, __shfl_xor_sync(0xFFFFFFFF, mx, o));
    }
    if (lane == 0) { redmn[warp] = mn; redmx[warp] = mx; }
    __syncthreads();
    if (warp == 0) {
        float fmn = redmn[lane], fmx = redmx[lane];
        #pragma unroll
        for (int o = 16; o; o >>= 1) {
            fmn = fminf(fmn, __shfl_xor_sync(0xFFFFFFFF, fmn, o));
            fmx = fmaxf(fmx, __shfl_xor_sync(0xFFFFFFFF, fmx, o));
        }
        if (lane == 0) {
            atomicMinF(&g_minb[c], fmn);
            atomicMaxF(&g_maxb[c], fmx);
        }
    }
}

// ---------------------------------------------------------------------------
// 3) Per-channel loss -> atomicAdd into out[0]; then reset channel state
//    (g_cnt, g_flag, minb/maxb) for the next graph replay. grid (CC), 128 thr.
__global__ void k_loss(const float* __restrict__ blob,
                       const int*   __restrict__ labels,
                       float* __restrict__ out) {
    int c = blockIdx.x, t = threadIdx.x;
    bool valid = (labels[c] == 1);
    const float* B = blob + c * hh * ww;

    float cmax = 0.f;
    for (int i = 0; i < hh; ++i) cmax = fmaxf(cmax, B[i * ww + t]);
    float rmax = 0.f;
    for (int j = 0; j < ww; ++j) rmax = fmaxf(rmax, B[t * ww + j]);
    cmax = fminf(fmaxf(cmax, EPSF), 1.f - EPSF);
    rmax = fminf(fmaxf(rmax, EPSF), 1.f - EPSF);

    float vx, vy;
    if (valid) {
        float mnv = __int_as_float(g_minb[c]);
        float mxv = __int_as_float(g_maxb[c]);
        float thr = mnv + 0.5f * (mxv - mnv + EPSF);   // normalized >= 0.5
        float scol = -3.4e38f, srow = -3.4e38f;
        for (int i = 0; i < hh; ++i) scol = fmaxf(scol, g_Rm[c][i][t]);
        for (int j = 0; j < ww; ++j) srow = fmaxf(srow, g_Rm[c][t][j]);
        vx = (scol >= thr) ? -logf(cmax) : 0.f;
        vy = (srow >= thr) ? -logf(rmax) : 0.f;
    } else {
        vx = -logf(1.f - cmax);
        vy = -logf(1.f - rmax);
    }

    __shared__ float sx[128], sy[128];
    sx[t] = vx; sy[t] = vy;
    __syncthreads();
    for (int o = 64; o; o >>= 1) {
        if (t < o) { sx[t] += sx[t + o]; sy[t] += sy[t + o]; }
        __syncthreads();
    }
    if (t == 0) {
        float vc = 0.f;
        for (int k = 0; k < CC; ++k) vc += (labels[k] == 1) ? 1.f : 0.f;
        float nvc = (float)CC - vc;
        float denom = valid ? vc : nvc;
        atomicAdd(out, sx[0] / (denom * (float)ww) + sy[0] / (denom * (float)hh));
    }

    // Self-clean for the next launch (all reads above are done).
    __syncthreads();
    if (t < NSEG) { g_cnt[c][t] = 0; g_flag[c][t] = 0; }
    if (t == 0)   { g_minb[c] = PINF; g_maxb[c] = NINF; }
}

// ---------------------------------------------------------------------------
extern "C" void kernel_launch(void* const* d_in, const int* in_sizes, int n_in,
                              void* d_out, int out_size) {
    // metadata order: mil_result(unused), refine_result, blob_conv, rois, labels, H, W
    const float* refine = (const float*)d_in[1];
    const float* blob   = (const float*)d_in[2];
    const float* rois   = (const float*)d_in[3];
    const int*   labels = (const int*)  d_in[4];
    int R = in_sizes[3] / 5;
    float* out = (float*)d_out;

    k_scatter<<<dim3((R + 255) / 256, CC), 256>>>(refine, rois, labels, R, out);
    k_AB     <<<dim3(NSEG, CC), 1024>>>(labels);
    k_loss   <<<CC, 128>>>(blob, labels, out);
}

// round 11
// speedup vs baseline: 1.3831x; 1.3831x over previous
#include <cuda_runtime.h>

// Problem-fixed shapes (setup_inputs): R=4000, C=20, K=3, H=W=1024, h=w=128.
#define HH 1024
#define WW 1024
#define CC 20
#define hh 128
#define ww 128
#define C1 21      // refine_result last dim = C+1
#define EPSF 1e-6f
#define NSEG 64
#define SEGH 16                 // rows per segment
#define MAXB 16384              // events per (c,seg) bucket; hard max = 4*R = 16000
#define PROWS 8                 // rows per smem phase in k_B (2 phases)
#define PINF 0x7F7FFFFF         // bits of +3.4028e38f
#define NINF 0xFF7FFFFF         // bits of -3.4028e38f

// Static scratch (no runtime allocation). Zero/static-initialized; every
// launch restores the invariant state it started from (self-cleaning).
__device__ int2  g_ev [CC][NSEG][MAXB];     // events (order irrelevant)
__device__ int   g_cnt[CC][NSEG];           // bucket sizes (reset by k_loss)
__device__ float g_seg[CC][NSEG][WW];       // per-segment column-sum PREFIX over x
__device__ float g_Rm[CC][hh][ww];          // sampled integral-image values
__device__ int   g_minb[CC] = {PINF,PINF,PINF,PINF,PINF,PINF,PINF,PINF,PINF,PINF,
                               PINF,PINF,PINF,PINF,PINF,PINF,PINF,PINF,PINF,PINF};
__device__ int   g_maxb[CC] = {NINF,NINF,NINF,NINF,NINF,NINF,NINF,NINF,NINF,NINF,
                               NINF,NINF,NINF,NINF,NINF,NINF,NINF,NINF,NINF,NINF};

__device__ __forceinline__ void atomicMinF(int* addr, float v) {
    int old = *addr;
    while (__int_as_float(old) > v) {
        int assumed = old;
        old = atomicCAS(addr, assumed, __float_as_int(v));
        if (old == assumed) break;
    }
}
__device__ __forceinline__ void atomicMaxF(int* addr, float v) {
    int old = *addr;
    while (__int_as_float(old) < v) {
        int assumed = old;
        old = atomicCAS(addr, assumed, __float_as_int(v));
        if (old == assumed) break;
    }
}

// ---------------------------------------------------------------------------
// 1) Scores + sparse event emission; also zeroes the output scalar.
//    One thread per (roi, class) with c contiguous -> coalesced refine reads.
__device__ __forceinline__ void emit_row(int c, int y, int x1, float s1, int x2, float s2) {
    if (y >= HH) return;                   // reference clips row H away via M[:H]
    int seg = y >> 4, yl = y & (SEGH - 1);
    int2 e1 = make_int2(x1 | (yl << 10), __float_as_int(s1));
    if (x2 < WW) {
        int idx = atomicAdd(&g_cnt[c][seg], 2);
        g_ev[c][seg][idx]     = e1;
        g_ev[c][seg][idx + 1] = make_int2(x2 | (yl << 10), __float_as_int(s2));
    } else {
        int idx = atomicAdd(&g_cnt[c][seg], 1);
        g_ev[c][seg][idx] = e1;
    }
}

__global__ void k_scatter(const float* __restrict__ refine,
                          const float* __restrict__ rois,
                          const int*   __restrict__ labels,
                          int R, float* __restrict__ out) {
    int idx = blockIdx.x * blockDim.x + threadIdx.x;
    if (idx == 0) out[0] = 0.f;            // k_loss accumulates into this later
    if (idx >= R * CC) return;
    int r = idx / CC, c = idx - r * CC;    // lanes span c -> coalesced refine
    if (labels[c] != 1) return;            // scores *= vmf
    int base = r * C1 + c + 1;             // avg[:,1:]
    float s = (refine[base] + refine[R * C1 + base] + refine[2 * R * C1 + base]) * (1.0f / 3.0f);
    if (s < 0.3f) return;                  // SCORE_THRES
    int x1 = (int)rois[r * 5 + 1];
    int y1 = (int)rois[r * 5 + 2];
    int x2 = (int)rois[r * 5 + 3];
    int y2 = (int)rois[r * 5 + 4];
    // M(y,x) = sum s * [y1<=y<y2] * [x1<=x<x2]
    emit_row(c, y1, x1,  s, x2, -s);
    emit_row(c, y2, x1, -s, x2,  s);
}

// ---------------------------------------------------------------------------
// 2) Per bucket: column-sum prefix g_seg[c][seg][x] (smem scatter + shfl scan).
//    grid (NSEG, CC), 1024 thr.
__global__ __launch_bounds__(1024) void k_A(const int* __restrict__ labels) {
    int c = blockIdx.y;
    if (labels[c] != 1) return;
    int seg = blockIdx.x, t = threadIdx.x;
    int lane = t & 31, warp = t >> 5;

    __shared__ float arr[WW];
    __shared__ float wsum[32];

    arr[t] = 0.f;
    __syncthreads();

    int E = g_cnt[c][seg];
    for (int i = t; i < E; i += 1024) {
        int2 e = g_ev[c][seg][i];
        atomicAdd(&arr[e.x & 0x3FF], __int_as_float(e.y));
    }
    __syncthreads();

    // Warp-level inclusive scan of arr[t] (1024 columns).
    float v = arr[t];
    #pragma unroll
    for (int o = 1; o < 32; o <<= 1) {
        float n = __shfl_up_sync(0xFFFFFFFF, v, o);
        if (lane >= o) v += n;
    }
    if (lane == 31) wsum[warp] = v;
    __syncthreads();
    if (warp == 0) {
        float w = wsum[lane];
        #pragma unroll
        for (int o = 1; o < 32; o <<= 1) {
            float n = __shfl_up_sync(0xFFFFFFFF, w, o);
            if (lane >= o) w += n;
        }
        wsum[lane] = w;
    }
    __syncthreads();
    if (warp > 0) v += wsum[warp - 1];
    g_seg[c][seg][t] = v;
}

// ---------------------------------------------------------------------------
// 3) Column scan via smem difference-array + per-row parallel prefix.
//    Thread = one column. 16 rows in 2 phases of 8:
//    zero diff -> parallel event scatter -> 8 warp scans (ILP) ->
//    warps 0..7 compute cross-warp EXCLUSIVE offsets in parallel ->
//    ordered row accumulation with min/max + stride-8 samples.
//    grid (NSEG, CC), 1024 thr.
__global__ __launch_bounds__(1024) void k_B(const int* __restrict__ labels) {
    int c = blockIdx.y;
    if (labels[c] != 1) return;
    int seg = blockIdx.x, x = threadIdx.x;
    int lane = x & 31, warp = x >> 5;

    __shared__ float diff[PROWS][WW];    // 32 KB
    __shared__ float wsum[PROWS][32];    // per-row warp partials -> exclusives
    __shared__ float redmn[32], redmx[32];

    // Base: sum of segment prefixes above this segment (L2-resident, batched).
    float run = 0.f;
    {
        int s = 0;
        for (; s + 8 <= seg; s += 8) {   // 8 independent loads per batch (MLP)
            float v0 = g_seg[c][s + 0][x], v1 = g_seg[c][s + 1][x];
            float v2 = g_seg[c][s + 2][x], v3 = g_seg[c][s + 3][x];
            float v4 = g_seg[c][s + 4][x], v5 = g_seg[c][s + 5][x];
            float v6 = g_seg[c][s + 6][x], v7 = g_seg[c][s + 7][x];
            run += ((v0 + v1) + (v2 + v3)) + ((v4 + v5) + (v6 + v7));
        }
        for (; s < seg; ++s) run += g_seg[c][s][x];
    }

    float mn = 3.4e38f, mx = -3.4e38f;
    int E = g_cnt[c][seg];

    #pragma unroll
    for (int p = 0; p < SEGH / PROWS; ++p) {
        #pragma unroll
        for (int r = 0; r < PROWS; ++r) diff[r][x] = 0.f;
        __syncthreads();

        // Parallel event scatter (order irrelevant).
        for (int i = x; i < E; i += 1024) {
            int2 e = g_ev[c][seg][i];
            int yl = e.x >> 10;
            if ((yl >> 3) == p)
                atomicAdd(&diff[yl & 7][e.x & 0x3FF], __int_as_float(e.y));
        }
        __syncthreads();

        // Per-row warp scans (8 independent -> ILP hides shfl latency).
        float varr[PROWS];
        #pragma unroll
        for (int r = 0; r < PROWS; ++r) {
            float v = diff[r][x];
            #pragma unroll
            for (int o = 1; o < 32; o <<= 1) {
                float n = __shfl_up_sync(0xFFFFFFFF, v, o);
                if (lane >= o) v += n;
            }
            varr[r] = v;
            if (lane == 31) wsum[r][warp] = v;
        }
        __syncthreads();

        // Warps 0..7 convert their row's warp sums to EXCLUSIVE offsets (parallel).
        if (warp < PROWS) {
            float w = wsum[warp][lane];
            #pragma unroll
            for (int o = 1; o < 32; o <<= 1) {
                float n = __shfl_up_sync(0xFFFFFFFF, w, o);
                if (lane >= o) w += n;
            }
            float excl = __shfl_up_sync(0xFFFFFFFF, w, 1);
            wsum[warp][lane] = (lane == 0) ? 0.f : excl;
        }
        __syncthreads();

        // Accumulate rows in order: P_r = varr[r] + exclusive warp offset.
        #pragma unroll
        for (int r = 0; r < PROWS; ++r) {
            run += varr[r] + wsum[r][warp];
            mn = fminf(mn, run);
            mx = fmaxf(mx, run);
            if (r == 0 && (x & 7) == 0)      // sampled row (multiple of 8)
                g_Rm[c][seg * 2 + p][x >> 3] = run;
        }
        __syncthreads();                     // smem reuse next phase
    }

    // Block-wide min/max reduce.
    #pragma unroll
    for (int o = 16; o; o >>= 1) {
        mn = fminf(mn, __shfl_xor_sync(0xFFFFFFFF, mn, o));
        mx = fmaxf(mx, __shfl_xor_sync(0xFFFFFFFF, mx, o));
    }
    if (lane == 0) { redmn[warp] = mn; redmx[warp] = mx; }
    __syncthreads();
    if (warp == 0) {
        float fmn = redmn[lane], fmx = redmx[lane];
        #pragma unroll
        for (int o = 16; o; o >>= 1) {
            fmn = fminf(fmn, __shfl_xor_sync(0xFFFFFFFF, fmn, o));
            fmx = fmaxf(fmx, __shfl_xor_sync(0xFFFFFFFF, fmx, o));
        }
        if (lane == 0) {
            atomicMinF(&g_minb[c], fmn);
            atomicMaxF(&g_maxb[c], fmx);
        }
    }
}

// ---------------------------------------------------------------------------
// 4) Per-channel loss -> atomicAdd into out[0]; then reset channel state
//    (g_cnt, minb/maxb) for the next graph replay. grid (CC), 128 thr.
__global__ void k_loss(const float* __restrict__ blob,
                       const int*   __restrict__ labels,
                       float* __restrict__ out) {
    int c = blockIdx.x, t = threadIdx.x;
    bool valid = (labels[c] == 1);
    const float* B = blob + c * hh * ww;

    float cmax = 0.f;
    for (int i = 0; i < hh; ++i) cmax = fmaxf(cmax, B[i * ww + t]);
    float rmax = 0.f;
    for (int j = 0; j < ww; ++j) rmax = fmaxf(rmax, B[t * ww + j]);
    cmax = fminf(fmaxf(cmax, EPSF), 1.f - EPSF);
    rmax = fminf(fmaxf(rmax, EPSF), 1.f - EPSF);

    float vx, vy;
    if (valid) {
        float mnv = __int_as_float(g_minb[c]);
        float mxv = __int_as_float(g_maxb[c]);
        float thr = mnv + 0.5f * (mxv - mnv + EPSF);   // normalized >= 0.5
        float scol = -3.4e38f, srow = -3.4e38f;
        for (int i = 0; i < hh; ++i) scol = fmaxf(scol, g_Rm[c][i][t]);
        for (int j = 0; j < ww; ++j) srow = fmaxf(srow, g_Rm[c][t][j]);
        vx = (scol >= thr) ? -logf(cmax) : 0.f;
        vy = (srow >= thr) ? -logf(rmax) : 0.f;
    } else {
        vx = -logf(1.f - cmax);
        vy = -logf(1.f - rmax);
    }

    __shared__ float sx[128], sy[128];
    sx[t] = vx; sy[t] = vy;
    __syncthreads();
    for (int o = 64; o; o >>= 1) {
        if (t < o) { sx[t] += sx[t + o]; sy[t] += sy[t + o]; }
        __syncthreads();
    }
    if (t == 0) {
        float vc = 0.f;
        for (int k = 0; k < CC; ++k) vc += (labels[k] == 1) ? 1.f : 0.f;
        float nvc = (float)CC - vc;
        float denom = valid ? vc : nvc;
        atomicAdd(out, sx[0] / (denom * (float)ww) + sy[0] / (denom * (float)hh));
    }

    // Self-clean for the next launch (all reads above are done).
    __syncthreads();
    if (t < NSEG) g_cnt[c][t] = 0;
    if (t == 0)   { g_minb[c] = PINF; g_maxb[c] = NINF; }
}

// ---------------------------------------------------------------------------
extern "C" void kernel_launch(void* const* d_in, const int* in_sizes, int n_in,
                              void* d_out, int out_size) {
    // metadata order: mil_result(unused), refine_result, blob_conv, rois, labels, H, W
    const float* refine = (const float*)d_in[1];
    const float* blob   = (const float*)d_in[2];
    const float* rois   = (const float*)d_in[3];
    const int*   labels = (const int*)  d_in[4];
    int R = in_sizes[3] / 5;
    float* out = (float*)d_out;

    int total = R * CC;
    k_scatter<<<(total + 255) / 256, 256>>>(refine, rois, labels, R, out);
    k_A      <<<dim3(NSEG, CC), 1024>>>(labels);
    k_B      <<<dim3(NSEG, CC), 1024>>>(labels);
    k_loss   <<<CC, 128>>>(blob, labels, out);
}

// round 12
// speedup vs baseline: 1.6478x; 1.1914x over previous
#include <cuda_runtime.h>

// Problem-fixed shapes (setup_inputs): R=4000, C=20, K=3, H=W=1024, h=w=128.
#define HH 1024
#define WW 1024
#define CC 20
#define hh 128
#define ww 128
#define C1 21      // refine_result last dim = C+1
#define EPSF 1e-6f
#define NSEG 64
#define SEGH 16                 // rows per segment
#define MAXB 16384              // events per (c,seg) bucket; hard max = 4*R = 16000
#define PROWS 8                 // rows per smem phase in k_B (2 phases)
#define PINF 0x7F7FFFFF         // bits of +3.4028e38f
#define NINF 0xFF7FFFFF         // bits of -3.4028e38f

// Static scratch (no runtime allocation). Zero/static-initialized; every
// launch restores the invariant state it started from (self-cleaning).
__device__ int2  g_ev [CC][NSEG][MAXB];     // events (order irrelevant)
__device__ int   g_cnt[CC][NSEG];           // bucket sizes (reset by k_loss)
__device__ float g_seg[CC][NSEG][WW];       // per-segment column-sum PREFIX over x
__device__ float g_Rm[CC][hh][ww];          // sampled integral-image values
__device__ int   g_minb[CC] = {PINF,PINF,PINF,PINF,PINF,PINF,PINF,PINF,PINF,PINF,
                               PINF,PINF,PINF,PINF,PINF,PINF,PINF,PINF,PINF,PINF};
__device__ int   g_maxb[CC] = {NINF,NINF,NINF,NINF,NINF,NINF,NINF,NINF,NINF,NINF,
                               NINF,NINF,NINF,NINF,NINF,NINF,NINF,NINF,NINF,NINF};

__device__ __forceinline__ void atomicMinF(int* addr, float v) {
    int old = *addr;
    while (__int_as_float(old) > v) {
        int assumed = old;
        old = atomicCAS(addr, assumed, __float_as_int(v));
        if (old == assumed) break;
    }
}
__device__ __forceinline__ void atomicMaxF(int* addr, float v) {
    int old = *addr;
    while (__int_as_float(old) < v) {
        int assumed = old;
        old = atomicCAS(addr, assumed, __float_as_int(v));
        if (old == assumed) break;
    }
}

// ---------------------------------------------------------------------------
// 1) Scores + sparse event emission; also zeroes the output scalar.
//    One thread per (roi, class) with c contiguous -> coalesced refine reads.
__device__ __forceinline__ void emit_row(int c, int y, int x1, float s1, int x2, float s2) {
    if (y >= HH) return;                   // reference clips row H away via M[:H]
    int seg = y >> 4, yl = y & (SEGH - 1);
    int2 e1 = make_int2(x1 | (yl << 10), __float_as_int(s1));
    if (x2 < WW) {
        int idx = atomicAdd(&g_cnt[c][seg], 2);
        g_ev[c][seg][idx]     = e1;
        g_ev[c][seg][idx + 1] = make_int2(x2 | (yl << 10), __float_as_int(s2));
    } else {
        int idx = atomicAdd(&g_cnt[c][seg], 1);
        g_ev[c][seg][idx] = e1;
    }
}

__global__ void k_scatter(const float* __restrict__ refine,
                          const float* __restrict__ rois,
                          const int*   __restrict__ labels,
                          int R, float* __restrict__ out) {
    int idx = blockIdx.x * blockDim.x + threadIdx.x;
    if (idx == 0) out[0] = 0.f;            // k_loss accumulates into this later
    if (idx >= R * CC) return;
    int r = idx / CC, c = idx - r * CC;    // lanes span c -> coalesced refine
    if (labels[c] != 1) return;            // scores *= vmf
    int base = r * C1 + c + 1;             // avg[:,1:]
    float s = (refine[base] + refine[R * C1 + base] + refine[2 * R * C1 + base]) * (1.0f / 3.0f);
    if (s < 0.3f) return;                  // SCORE_THRES
    int x1 = (int)rois[r * 5 + 1];
    int y1 = (int)rois[r * 5 + 2];
    int x2 = (int)rois[r * 5 + 3];
    int y2 = (int)rois[r * 5 + 4];
    // M(y,x) = sum s * [y1<=y<y2] * [x1<=x<x2]
    emit_row(c, y1, x1,  s, x2, -s);
    emit_row(c, y2, x1, -s, x2,  s);
}

// ---------------------------------------------------------------------------
// 2) Per bucket: column-sum prefix g_seg[c][seg][x] (smem scatter + shfl scan).
//    grid (NSEG, CC), 1024 thr.
__global__ __launch_bounds__(1024) void k_A(const int* __restrict__ labels) {
    int c = blockIdx.y;
    if (labels[c] != 1) return;
    int seg = blockIdx.x, t = threadIdx.x;
    int lane = t & 31, warp = t >> 5;

    __shared__ float arr[WW];
    __shared__ float wsum[32];

    arr[t] = 0.f;
    __syncthreads();

    int E = g_cnt[c][seg];
    for (int i = t; i < E; i += 1024) {
        int2 e = g_ev[c][seg][i];
        atomicAdd(&arr[e.x & 0x3FF], __int_as_float(e.y));
    }
    __syncthreads();

    // Warp-level inclusive scan of arr[t] (1024 columns).
    float v = arr[t];
    #pragma unroll
    for (int o = 1; o < 32; o <<= 1) {
        float n = __shfl_up_sync(0xFFFFFFFF, v, o);
        if (lane >= o) v += n;
    }
    if (lane == 31) wsum[warp] = v;
    __syncthreads();
    if (warp == 0) {
        float w = wsum[lane];
        #pragma unroll
        for (int o = 1; o < 32; o <<= 1) {
            float n = __shfl_up_sync(0xFFFFFFFF, w, o);
            if (lane >= o) w += n;
        }
        wsum[lane] = w;
    }
    __syncthreads();
    if (warp > 0) v += wsum[warp - 1];
    g_seg[c][seg][t] = v;
}

// ---------------------------------------------------------------------------
// 3) Column scan via smem difference-array + per-row parallel prefix.
//    grid (NSEG, CC), 1024 thr. (Unchanged from best-known version.)
__global__ __launch_bounds__(1024) void k_B(const int* __restrict__ labels) {
    int c = blockIdx.y;
    if (labels[c] != 1) return;
    int seg = blockIdx.x, x = threadIdx.x;
    int lane = x & 31, warp = x >> 5;

    __shared__ float diff[PROWS][WW];    // 32 KB
    __shared__ float wsum[PROWS][32];    // per-row warp partials -> exclusives
    __shared__ float redmn[32], redmx[32];

    // Base: sum of segment prefixes above this segment (L2-resident, batched).
    float run = 0.f;
    {
        int s = 0;
        for (; s + 8 <= seg; s += 8) {   // 8 independent loads per batch (MLP)
            float v0 = g_seg[c][s + 0][x], v1 = g_seg[c][s + 1][x];
            float v2 = g_seg[c][s + 2][x], v3 = g_seg[c][s + 3][x];
            float v4 = g_seg[c][s + 4][x], v5 = g_seg[c][s + 5][x];
            float v6 = g_seg[c][s + 6][x], v7 = g_seg[c][s + 7][x];
            run += ((v0 + v1) + (v2 + v3)) + ((v4 + v5) + (v6 + v7));
        }
        for (; s < seg; ++s) run += g_seg[c][s][x];
    }

    float mn = 3.4e38f, mx = -3.4e38f;
    int E = g_cnt[c][seg];

    #pragma unroll
    for (int p = 0; p < SEGH / PROWS; ++p) {
        #pragma unroll
        for (int r = 0; r < PROWS; ++r) diff[r][x] = 0.f;
        __syncthreads();

        for (int i = x; i < E; i += 1024) {
            int2 e = g_ev[c][seg][i];
            int yl = e.x >> 10;
            if ((yl >> 3) == p)
                atomicAdd(&diff[yl & 7][e.x & 0x3FF], __int_as_float(e.y));
        }
        __syncthreads();

        float varr[PROWS];
        #pragma unroll
        for (int r = 0; r < PROWS; ++r) {
            float v = diff[r][x];
            #pragma unroll
            for (int o = 1; o < 32; o <<= 1) {
                float n = __shfl_up_sync(0xFFFFFFFF, v, o);
                if (lane >= o) v += n;
            }
            varr[r] = v;
            if (lane == 31) wsum[r][warp] = v;
        }
        __syncthreads();

        if (warp < PROWS) {
            float w = wsum[warp][lane];
            #pragma unroll
            for (int o = 1; o < 32; o <<= 1) {
                float n = __shfl_up_sync(0xFFFFFFFF, w, o);
                if (lane >= o) w += n;
            }
            float excl = __shfl_up_sync(0xFFFFFFFF, w, 1);
            wsum[warp][lane] = (lane == 0) ? 0.f : excl;
        }
        __syncthreads();

        #pragma unroll
        for (int r = 0; r < PROWS; ++r) {
            run += varr[r] + wsum[r][warp];
            mn = fminf(mn, run);
            mx = fmaxf(mx, run);
            if (r == 0 && (x & 7) == 0)      // sampled row (multiple of 8)
                g_Rm[c][seg * 2 + p][x >> 3] = run;
        }
        __syncthreads();                     // smem reuse next phase
    }

    #pragma unroll
    for (int o = 16; o; o >>= 1) {
        mn = fminf(mn, __shfl_xor_sync(0xFFFFFFFF, mn, o));
        mx = fmaxf(mx, __shfl_xor_sync(0xFFFFFFFF, mx, o));
    }
    if (lane == 0) { redmn[warp] = mn; redmx[warp] = mx; }
    __syncthreads();
    if (warp == 0) {
        float fmn = redmn[lane], fmx = redmx[lane];
        #pragma unroll
        for (int o = 16; o; o >>= 1) {
            fmn = fminf(fmn, __shfl_xor_sync(0xFFFFFFFF, fmn, o));
            fmx = fmaxf(fmx, __shfl_xor_sync(0xFFFFFFFF, fmx, o));
        }
        if (lane == 0) {
            atomicMinF(&g_minb[c], fmn);
            atomicMaxF(&g_maxb[c], fmx);
        }
    }
}

// ---------------------------------------------------------------------------
// 4) Per-channel loss with WIDE parallelism: 1024 threads/block.
//    Col max: thread (rg,col) scans 16 rows (coalesced, MLP=16).
//    Row max: thread (row,k) scans 16 consecutive cols (L1/L2-resident).
//    Same over g_Rm for valid channels. Then 128 threads compute -log terms,
//    4-warp reduce, atomicAdd into out[0]; self-clean. grid (CC), 1024 thr.
__global__ __launch_bounds__(1024) void k_loss(const float* __restrict__ blob,
                                               const int*   __restrict__ labels,
                                               float* __restrict__ out) {
    int c = blockIdx.x, t = threadIdx.x;
    bool valid = (labels[c] == 1);          // block-uniform
    const float* B  = blob + c * hh * ww;
    const float* Rm = &g_Rm[c][0][0];

    __shared__ float part[8][128];
    __shared__ float cmax_s[128], rmax_s[128];
    __shared__ float colR_s[128], rowR_s[128];
    __shared__ float red[8];

    int col = t & 127, rg = t >> 7;         // pass-1 mapping (8 x 128)
    int row = t >> 3,  k8 = t & 7;          // pass-2 mapping (128 x 8)

    // --- blob col max ---
    float m = 0.f;
    #pragma unroll
    for (int j = 0; j < 16; ++j) m = fmaxf(m, B[(rg * 16 + j) * ww + col]);
    part[rg][col] = m;
    __syncthreads();
    if (t < 128) {
        float v = part[0][t];
        #pragma unroll
        for (int k = 1; k < 8; ++k) v = fmaxf(v, part[k][t]);
        cmax_s[t] = v;
    }
    __syncthreads();

    // --- blob row max ---
    m = 0.f;
    #pragma unroll
    for (int j = 0; j < 16; ++j) m = fmaxf(m, B[row * ww + k8 * 16 + j]);
    part[k8][row] = m;
    __syncthreads();
    if (t < 128) {
        float v = part[0][t];
        #pragma unroll
        for (int k = 1; k < 8; ++k) v = fmaxf(v, part[k][t]);
        rmax_s[t] = v;
    }
    __syncthreads();

    if (valid) {
        // --- Rm col max ---
        m = -3.4e38f;
        #pragma unroll
        for (int j = 0; j < 16; ++j) m = fmaxf(m, Rm[(rg * 16 + j) * ww + col]);
        part[rg][col] = m;
        __syncthreads();
        if (t < 128) {
            float v = part[0][t];
            #pragma unroll
            for (int k = 1; k < 8; ++k) v = fmaxf(v, part[k][t]);
            colR_s[t] = v;
        }
        __syncthreads();
        // --- Rm row max ---
        m = -3.4e38f;
        #pragma unroll
        for (int j = 0; j < 16; ++j) m = fmaxf(m, Rm[row * ww + k8 * 16 + j]);
        part[k8][row] = m;
        __syncthreads();
        if (t < 128) {
            float v = part[0][t];
            #pragma unroll
            for (int k = 1; k < 8; ++k) v = fmaxf(v, part[k][t]);
            rowR_s[t] = v;
        }
        __syncthreads();
    }

    // --- loss terms over the 128 cols/rows ---
    float vx = 0.f, vy = 0.f;
    if (t < 128) {
        float cmax = fminf(fmaxf(cmax_s[t], EPSF), 1.f - EPSF);
        float rmax = fminf(fmaxf(rmax_s[t], EPSF), 1.f - EPSF);
        if (valid) {
            float mnv = __int_as_float(g_minb[c]);
            float mxv = __int_as_float(g_maxb[c]);
            float thr = mnv + 0.5f * (mxv - mnv + EPSF);   // normalized >= 0.5
            vx = (colR_s[t] >= thr) ? -logf(cmax) : 0.f;
            vy = (rowR_s[t] >= thr) ? -logf(rmax) : 0.f;
        } else {
            vx = -logf(1.f - cmax);
            vy = -logf(1.f - rmax);
        }
    }
    // Reduce vx+weighted vy over threads 0..127 (warps 0..3).
    int lane = t & 31, warp = t >> 5;
    #pragma unroll
    for (int o = 16; o; o >>= 1) {
        vx += __shfl_xor_sync(0xFFFFFFFF, vx, o);
        vy += __shfl_xor_sync(0xFFFFFFFF, vy, o);
    }
    if (lane == 0 && warp < 4) { part[0][warp] = vx; part[0][warp + 4] = vy; }
    __syncthreads();
    if (t == 0) {
        float sx = part[0][0] + part[0][1] + part[0][2] + part[0][3];
        float sy = part[0][4] + part[0][5] + part[0][6] + part[0][7];
        float vc = 0.f;
        for (int k = 0; k < CC; ++k) vc += (labels[k] == 1) ? 1.f : 0.f;
        float nvc = (float)CC - vc;
        float denom = valid ? vc : nvc;
        atomicAdd(out, sx / (denom * (float)ww) + sy / (denom * (float)hh));
    }

    // Self-clean for the next launch (all reads above are done).
    __syncthreads();
    if (t < NSEG) g_cnt[c][t] = 0;
    if (t == 0)   { g_minb[c] = PINF; g_maxb[c] = NINF; }
}

// ---------------------------------------------------------------------------
extern "C" void kernel_launch(void* const* d_in, const int* in_sizes, int n_in,
                              void* d_out, int out_size) {
    // metadata order: mil_result(unused), refine_result, blob_conv, rois, labels, H, W
    const float* refine = (const float*)d_in[1];
    const float* blob   = (const float*)d_in[2];
    const float* rois   = (const float*)d_in[3];
    const int*   labels = (const int*)  d_in[4];
    int R = in_sizes[3] / 5;
    float* out = (float*)d_out;

    int total = R * CC;
    k_scatter<<<(total + 255) / 256, 256>>>(refine, rois, labels, R, out);
    k_A      <<<dim3(NSEG, CC), 1024>>>(labels);
    k_B      <<<dim3(NSEG, CC), 1024>>>(labels);
    k_loss   <<<CC, 1024>>>(blob, labels, out);
}

// round 13
// speedup vs baseline: 1.7597x; 1.0679x over previous
#include <cuda_runtime.h>

// Problem-fixed shapes (setup_inputs): R=4000, C=20, K=3, H=W=1024, h=w=128.
#define HH 1024
#define WW 1024
#define CC 20
#define hh 128
#define ww 128
#define C1 21      // refine_result last dim = C+1
#define EPSF 1e-6f
#define NSEG 64
#define SEGH 16                 // rows per segment
#define MAXB 16384              // events per (c,seg) bucket; hard max = 4*R = 16000
#define PROWS 8                 // rows per smem phase in k_B (2 phases)
#define NSLAB 8                 // blob-max slabs per channel (16 rows each)
#define PINF 0x7F7FFFFF         // bits of +3.4028e38f
#define NINF 0xFF7FFFFF         // bits of -3.4028e38f

// Static scratch (no runtime allocation). Zero/static-initialized; every
// launch restores the invariant state it started from (self-cleaning).
__device__ int2  g_ev [CC][NSEG][MAXB];     // events (order irrelevant)
__device__ int   g_cnt[CC][NSEG];           // bucket sizes (reset by k_loss)
__device__ float g_seg[CC][NSEG][WW];       // per-segment column-sum PREFIX over x
__device__ float g_Rm[CC][hh][ww];          // sampled integral-image values
__device__ float g_bcol[CC][NSLAB][ww];     // blob col-max partials (overwritten)
__device__ float g_brow[CC][hh];            // blob row maxes (overwritten)
__device__ int   g_minb[CC] = {PINF,PINF,PINF,PINF,PINF,PINF,PINF,PINF,PINF,PINF,
                               PINF,PINF,PINF,PINF,PINF,PINF,PINF,PINF,PINF,PINF};
__device__ int   g_maxb[CC] = {NINF,NINF,NINF,NINF,NINF,NINF,NINF,NINF,NINF,NINF,
                               NINF,NINF,NINF,NINF,NINF,NINF,NINF,NINF,NINF,NINF};

__device__ __forceinline__ void atomicMinF(int* addr, float v) {
    int old = *addr;
    while (__int_as_float(old) > v) {
        int assumed = old;
        old = atomicCAS(addr, assumed, __float_as_int(v));
        if (old == assumed) break;
    }
}
__device__ __forceinline__ void atomicMaxF(int* addr, float v) {
    int old = *addr;
    while (__int_as_float(old) < v) {
        int assumed = old;
        old = atomicCAS(addr, assumed, __float_as_int(v));
        if (old == assumed) break;
    }
}

// ---------------------------------------------------------------------------
// 1) Scores + sparse event emission; also zeroes the output scalar.
//    One thread per (roi, class) with c contiguous -> coalesced refine reads.
__device__ __forceinline__ void emit_row(int c, int y, int x1, float s1, int x2, float s2) {
    if (y >= HH) return;                   // reference clips row H away via M[:H]
    int seg = y >> 4, yl = y & (SEGH - 1);
    int2 e1 = make_int2(x1 | (yl << 10), __float_as_int(s1));
    if (x2 < WW) {
        int idx = atomicAdd(&g_cnt[c][seg], 2);
        g_ev[c][seg][idx]     = e1;
        g_ev[c][seg][idx + 1] = make_int2(x2 | (yl << 10), __float_as_int(s2));
    } else {
        int idx = atomicAdd(&g_cnt[c][seg], 1);
        g_ev[c][seg][idx] = e1;
    }
}

__global__ void k_scatter(const float* __restrict__ refine,
                          const float* __restrict__ rois,
                          const int*   __restrict__ labels,
                          int R, float* __restrict__ out) {
    int idx = blockIdx.x * blockDim.x + threadIdx.x;
    if (idx == 0) out[0] = 0.f;            // k_loss accumulates into this later
    if (idx >= R * CC) return;
    int r = idx / CC, c = idx - r * CC;    // lanes span c -> coalesced refine
    if (labels[c] != 1) return;            // scores *= vmf
    int base = r * C1 + c + 1;             // avg[:,1:]
    float s = (refine[base] + refine[R * C1 + base] + refine[2 * R * C1 + base]) * (1.0f / 3.0f);
    if (s < 0.3f) return;                  // SCORE_THRES
    int x1 = (int)rois[r * 5 + 1];
    int y1 = (int)rois[r * 5 + 2];
    int x2 = (int)rois[r * 5 + 3];
    int y2 = (int)rois[r * 5 + 4];
    // M(y,x) = sum s * [y1<=y<y2] * [x1<=x<x2]
    emit_row(c, y1, x1,  s, x2, -s);
    emit_row(c, y2, x1, -s, x2,  s);
}

// ---------------------------------------------------------------------------
// 2) grid (NSEG + NSLAB, CC), 1024 thr.
//    seg <  NSEG : per-bucket column-sum prefix g_seg (smem scatter+shfl scan).
//    seg >= NSEG : blob max slab (runs for ALL channels, overlaps with scans):
//                  col-max partials over 16 rows + final row maxes.
__global__ __launch_bounds__(1024) void k_A(const float* __restrict__ blob,
                                            const int* __restrict__ labels) {
    int c = blockIdx.y;
    int seg = blockIdx.x, t = threadIdx.x;
    int lane = t & 31, warp = t >> 5;

    __shared__ float arr[WW];
    __shared__ float wsum[32];
    __shared__ float p2[16][2];

    if (seg >= NSEG) {
        // ---- blob max slab (16 rows x 128 cols), every channel ----
        int slab = seg - NSEG;
        const float* B = blob + c * hh * ww + slab * 16 * ww;
        float* part = arr;                     // reuse arr as [8][128]
        int col = t & 127, j = t >> 7;         // j in 0..7
        float m = fmaxf(B[j * ww + col], B[(j + 8) * ww + col]);
        part[j * 128 + col] = m;
        __syncthreads();
        if (t < 128) {
            float v = part[t];
            #pragma unroll
            for (int k = 1; k < 8; ++k) v = fmaxf(v, part[k * 128 + t]);
            g_bcol[c][slab][t] = v;
        }
        // row maxes: rows of 64 threads (2 warps), 2 cols per thread.
        int rl = t >> 6, k = t & 63;
        float m2 = fmaxf(B[rl * ww + k], B[rl * ww + k + 64]);
        #pragma unroll
        for (int o = 16; o; o >>= 1) m2 = fmaxf(m2, __shfl_xor_sync(0xFFFFFFFF, m2, o));
        if (lane == 0) p2[rl][warp & 1] = m2;
        __syncthreads();
        if (t < 16) g_brow[c][slab * 16 + t] = fmaxf(p2[t][0], p2[t][1]);
        return;
    }

    if (labels[c] != 1) return;

    arr[t] = 0.f;
    __syncthreads();

    int E = g_cnt[c][seg];
    for (int i = t; i < E; i += 1024) {
        int2 e = g_ev[c][seg][i];
        atomicAdd(&arr[e.x & 0x3FF], __int_as_float(e.y));
    }
    __syncthreads();

    // Warp-level inclusive scan of arr[t] (1024 columns).
    float v = arr[t];
    #pragma unroll
    for (int o = 1; o < 32; o <<= 1) {
        float n = __shfl_up_sync(0xFFFFFFFF, v, o);
        if (lane >= o) v += n;
    }
    if (lane == 31) wsum[warp] = v;
    __syncthreads();
    if (warp == 0) {
        float w = wsum[lane];
        #pragma unroll
        for (int o = 1; o < 32; o <<= 1) {
            float n = __shfl_up_sync(0xFFFFFFFF, w, o);
            if (lane >= o) w += n;
        }
        wsum[lane] = w;
    }
    __syncthreads();
    if (warp > 0) v += wsum[warp - 1];
    g_seg[c][seg][t] = v;
}

// ---------------------------------------------------------------------------
// 3) Column scan via smem difference-array + per-row parallel prefix.
//    grid (NSEG, CC), 1024 thr. (Unchanged from best-known version.)
__global__ __launch_bounds__(1024) void k_B(const int* __restrict__ labels) {
    int c = blockIdx.y;
    if (labels[c] != 1) return;
    int seg = blockIdx.x, x = threadIdx.x;
    int lane = x & 31, warp = x >> 5;

    __shared__ float diff[PROWS][WW];    // 32 KB
    __shared__ float wsum[PROWS][32];    // per-row warp partials -> exclusives
    __shared__ float redmn[32], redmx[32];

    // Base: sum of segment prefixes above this segment (L2-resident, batched).
    float run = 0.f;
    {
        int s = 0;
        for (; s + 8 <= seg; s += 8) {   // 8 independent loads per batch (MLP)
            float v0 = g_seg[c][s + 0][x], v1 = g_seg[c][s + 1][x];
            float v2 = g_seg[c][s + 2][x], v3 = g_seg[c][s + 3][x];
            float v4 = g_seg[c][s + 4][x], v5 = g_seg[c][s + 5][x];
            float v6 = g_seg[c][s + 6][x], v7 = g_seg[c][s + 7][x];
            run += ((v0 + v1) + (v2 + v3)) + ((v4 + v5) + (v6 + v7));
        }
        for (; s < seg; ++s) run += g_seg[c][s][x];
    }

    float mn = 3.4e38f, mx = -3.4e38f;
    int E = g_cnt[c][seg];

    #pragma unroll
    for (int p = 0; p < SEGH / PROWS; ++p) {
        #pragma unroll
        for (int r = 0; r < PROWS; ++r) diff[r][x] = 0.f;
        __syncthreads();

        for (int i = x; i < E; i += 1024) {
            int2 e = g_ev[c][seg][i];
            int yl = e.x >> 10;
            if ((yl >> 3) == p)
                atomicAdd(&diff[yl & 7][e.x & 0x3FF], __int_as_float(e.y));
        }
        __syncthreads();

        float varr[PROWS];
        #pragma unroll
        for (int r = 0; r < PROWS; ++r) {
            float v = diff[r][x];
            #pragma unroll
            for (int o = 1; o < 32; o <<= 1) {
                float n = __shfl_up_sync(0xFFFFFFFF, v, o);
                if (lane >= o) v += n;
            }
            varr[r] = v;
            if (lane == 31) wsum[r][warp] = v;
        }
        __syncthreads();

        if (warp < PROWS) {
            float w = wsum[warp][lane];
            #pragma unroll
            for (int o = 1; o < 32; o <<= 1) {
                float n = __shfl_up_sync(0xFFFFFFFF, w, o);
                if (lane >= o) w += n;
            }
            float excl = __shfl_up_sync(0xFFFFFFFF, w, 1);
            wsum[warp][lane] = (lane == 0) ? 0.f : excl;
        }
        __syncthreads();

        #pragma unroll
        for (int r = 0; r < PROWS; ++r) {
            run += varr[r] + wsum[r][warp];
            mn = fminf(mn, run);
            mx = fmaxf(mx, run);
            if (r == 0 && (x & 7) == 0)      // sampled row (multiple of 8)
                g_Rm[c][seg * 2 + p][x >> 3] = run;
        }
        __syncthreads();                     // smem reuse next phase
    }

    #pragma unroll
    for (int o = 16; o; o >>= 1) {
        mn = fminf(mn, __shfl_xor_sync(0xFFFFFFFF, mn, o));
        mx = fmaxf(mx, __shfl_xor_sync(0xFFFFFFFF, mx, o));
    }
    if (lane == 0) { redmn[warp] = mn; redmx[warp] = mx; }
    __syncthreads();
    if (warp == 0) {
        float fmn = redmn[lane], fmx = redmx[lane];
        #pragma unroll
        for (int o = 16; o; o >>= 1) {
            fmn = fminf(fmn, __shfl_xor_sync(0xFFFFFFFF, fmn, o));
            fmx = fmaxf(fmx, __shfl_xor_sync(0xFFFFFFFF, fmx, o));
        }
        if (lane == 0) {
            atomicMinF(&g_minb[c], fmn);
            atomicMaxF(&g_maxb[c], fmx);
        }
    }
}

// ---------------------------------------------------------------------------
// 4) Per-channel loss from PRECOMPUTED blob maxes + L2-resident Rm maxes.
//    grid (CC), 1024 thr.
__global__ __launch_bounds__(1024) void k_loss(const int* __restrict__ labels,
                                               float* __restrict__ out) {
    int c = blockIdx.x, t = threadIdx.x;
    bool valid = (labels[c] == 1);          // block-uniform
    const float* Rm = &g_Rm[c][0][0];

    __shared__ float part[8][128];
    __shared__ float cmax_s[128], rmax_s[128];
    __shared__ float colR_s[128], rowR_s[128];

    // Blob maxes: combine 8 precomputed slab partials (tiny).
    if (t < 128) {
        float v = g_bcol[c][0][t];
        #pragma unroll
        for (int k = 1; k < NSLAB; ++k) v = fmaxf(v, g_bcol[c][k][t]);
        cmax_s[t] = v;
        rmax_s[t] = g_brow[c][t];
    }

    if (valid) {
        int col = t & 127, rg = t >> 7;     // 8 x 128
        int row = t >> 3,  k8 = t & 7;      // 128 x 8
        // --- Rm col max ---
        float m = -3.4e38f;
        #pragma unroll
        for (int j = 0; j < 16; ++j) m = fmaxf(m, Rm[(rg * 16 + j) * ww + col]);
        part[rg][col] = m;
        __syncthreads();
        if (t < 128) {
            float v = part[0][t];
            #pragma unroll
            for (int k = 1; k < 8; ++k) v = fmaxf(v, part[k][t]);
            colR_s[t] = v;
        }
        __syncthreads();
        // --- Rm row max ---
        m = -3.4e38f;
        #pragma unroll
        for (int j = 0; j < 16; ++j) m = fmaxf(m, Rm[row * ww + k8 * 16 + j]);
        part[k8][row] = m;
        __syncthreads();
        if (t < 128) {
            float v = part[0][t];
            #pragma unroll
            for (int k = 1; k < 8; ++k) v = fmaxf(v, part[k][t]);
            rowR_s[t] = v;
        }
    }
    __syncthreads();

    // --- loss terms over the 128 cols/rows ---
    float vx = 0.f, vy = 0.f;
    if (t < 128) {
        float cmax = fminf(fmaxf(cmax_s[t], EPSF), 1.f - EPSF);
        float rmax = fminf(fmaxf(rmax_s[t], EPSF), 1.f - EPSF);
        if (valid) {
            float mnv = __int_as_float(g_minb[c]);
            float mxv = __int_as_float(g_maxb[c]);
            float thr = mnv + 0.5f * (mxv - mnv + EPSF);   // normalized >= 0.5
            vx = (colR_s[t] >= thr) ? -logf(cmax) : 0.f;
            vy = (rowR_s[t] >= thr) ? -logf(rmax) : 0.f;
        } else {
            vx = -logf(1.f - cmax);
            vy = -logf(1.f - rmax);
        }
    }
    int lane = t & 31, warp = t >> 5;
    #pragma unroll
    for (int o = 16; o; o >>= 1) {
        vx += __shfl_xor_sync(0xFFFFFFFF, vx, o);
        vy += __shfl_xor_sync(0xFFFFFFFF, vy, o);
    }
    if (lane == 0 && warp < 4) { part[0][warp] = vx; part[0][warp + 4] = vy; }
    __syncthreads();
    if (t == 0) {
        float sx = part[0][0] + part[0][1] + part[0][2] + part[0][3];
        float sy = part[0][4] + part[0][5] + part[0][6] + part[0][7];
        float vc = 0.f;
        for (int k = 0; k < CC; ++k) vc += (labels[k] == 1) ? 1.f : 0.f;
        float nvc = (float)CC - vc;
        float denom = valid ? vc : nvc;
        atomicAdd(out, sx / (denom * (float)ww) + sy / (denom * (float)hh));
    }

    // Self-clean for the next launch (all reads above are done).
    __syncthreads();
    if (t < NSEG) g_cnt[c][t] = 0;
    if (t == 0)   { g_minb[c] = PINF; g_maxb[c] = NINF; }
}

// ---------------------------------------------------------------------------
extern "C" void kernel_launch(void* const* d_in, const int* in_sizes, int n_in,
                              void* d_out, int out_size) {
    // metadata order: mil_result(unused), refine_result, blob_conv, rois, labels, H, W
    const float* refine = (const float*)d_in[1];
    const float* blob   = (const float*)d_in[2];
    const float* rois   = (const float*)d_in[3];
    const int*   labels = (const int*)  d_in[4];
    int R = in_sizes[3] / 5;
    float* out = (float*)d_out;

    int total = R * CC;
    k_scatter<<<(total + 255) / 256, 256>>>(refine, rois, labels, R, out);
    k_A      <<<dim3(NSEG + NSLAB, CC), 1024>>>(blob, labels);
    k_B      <<<dim3(NSEG, CC), 1024>>>(labels);
    k_loss   <<<CC, 1024>>>(labels, out);
}